// round 14
// baseline (speedup 1.0000x reference)
#include <cuda_runtime.h>
#include <math.h>

// ---------------------------------------------------------------------------
// FSC loss, round 14: A unchanged from round 13 (DIF x2 -> rev7-transpose ->
// DIT x2 straight to global). B: single-line FFT phase (reg relief),
// algebraic product reform (cross/S/D), warp-shuffle bins flush.
// ---------------------------------------------------------------------------

#define S2   129      // kernel A transpose row stride (float2)
#define W2   33       // kernel B tile row stride (float2)
#define SMEM_A (128 * S2 * 8)                 // 132096 B
#define SMEM_B (2 * 128 * W2 * 8)             // 67584 B
#define PIF 3.14159265358979323846f

static __device__ float2 g_fft[8u * 128u * 128u * 128u];   // 134 MB scratch
static __device__ double g_acc[8][65][3];                  // num, d1, d2
static __device__ unsigned int g_ctr = 0;

__device__ __forceinline__ int rev7(int i) { return (int)(__brev((unsigned)i) >> 25); }

// 128-pt DIF FFT (single): natural input; output slot i holds X[rev7(i)].
__device__ __forceinline__ void fft128(float re[4], float im[4], int t,
                                       const float2* __restrict__ tw)
{
    {
        float2 w1 = tw[t], w2 = tw[t + 32];
        float ar, ai;
        ar = re[0] - re[2]; ai = im[0] - im[2];
        re[0] += re[2];     im[0] += im[2];
        re[2] = ar * w1.x - ai * w1.y; im[2] = ar * w1.y + ai * w1.x;
        ar = re[1] - re[3]; ai = im[1] - im[3];
        re[1] += re[3];     im[1] += im[3];
        re[3] = ar * w2.x - ai * w2.y; im[3] = ar * w2.y + ai * w2.x;
    }
    {
        float2 w3 = tw[2 * t];
        float ar, ai;
        ar = re[0] - re[1]; ai = im[0] - im[1];
        re[0] += re[1];     im[0] += im[1];
        re[1] = ar * w3.x - ai * w3.y; im[1] = ar * w3.y + ai * w3.x;
        ar = re[2] - re[3]; ai = im[2] - im[3];
        re[2] += re[3];     im[2] += im[3];
        re[3] = ar * w3.x - ai * w3.y; im[3] = ar * w3.y + ai * w3.x;
    }
#pragma unroll
    for (int m = 16; m >= 1; m >>= 1) {
        bool up = (t & m) != 0;
        int idx = up ? (64 / m) * (t & (m - 1)) : 0;
        float2 wm = tw[idx];
#pragma unroll
        for (int k = 0; k < 4; k++) {
            float pr = __shfl_xor_sync(0xffffffffu, re[k], m);
            float pi = __shfl_xor_sync(0xffffffffu, im[k], m);
            float sr = up ? pr - re[k] : re[k] + pr;
            float si = up ? pi - im[k] : im[k] + pi;
            re[k] = sr * wm.x - si * wm.y;
            im[k] = sr * wm.y + si * wm.x;
        }
    }
}

// 128-pt DIF FFT x2: two independent lines interleaved (ILP pairing).
__device__ __forceinline__ void fft128x2(float re[2][4], float im[2][4], int t,
                                         const float2* __restrict__ tw)
{
    {
        float2 w1 = tw[t], w2 = tw[t + 32];
#pragma unroll
        for (int j = 0; j < 2; j++) {
            float ar, ai;
            ar = re[j][0] - re[j][2]; ai = im[j][0] - im[j][2];
            re[j][0] += re[j][2];     im[j][0] += im[j][2];
            re[j][2] = ar * w1.x - ai * w1.y; im[j][2] = ar * w1.y + ai * w1.x;
            ar = re[j][1] - re[j][3]; ai = im[j][1] - im[j][3];
            re[j][1] += re[j][3];     im[j][1] += im[j][3];
            re[j][3] = ar * w2.x - ai * w2.y; im[j][3] = ar * w2.y + ai * w2.x;
        }
    }
    {
        float2 w3 = tw[2 * t];
#pragma unroll
        for (int j = 0; j < 2; j++) {
            float ar, ai;
            ar = re[j][0] - re[j][1]; ai = im[j][0] - im[j][1];
            re[j][0] += re[j][1];     im[j][0] += im[j][1];
            re[j][1] = ar * w3.x - ai * w3.y; im[j][1] = ar * w3.y + ai * w3.x;
            ar = re[j][2] - re[j][3]; ai = im[j][2] - im[j][3];
            re[j][2] += re[j][3];     im[j][2] += im[j][3];
            re[j][3] = ar * w3.x - ai * w3.y; im[j][3] = ar * w3.y + ai * w3.x;
        }
    }
#pragma unroll
    for (int m = 16; m >= 1; m >>= 1) {
        bool up = (t & m) != 0;
        int idx = up ? (64 / m) * (t & (m - 1)) : 0;
        float2 wm = tw[idx];
#pragma unroll
        for (int k = 0; k < 4; k++) {
            float pr0 = __shfl_xor_sync(0xffffffffu, re[0][k], m);
            float pi0 = __shfl_xor_sync(0xffffffffu, im[0][k], m);
            float pr1 = __shfl_xor_sync(0xffffffffu, re[1][k], m);
            float pi1 = __shfl_xor_sync(0xffffffffu, im[1][k], m);
            float sr0 = up ? pr0 - re[0][k] : re[0][k] + pr0;
            float si0 = up ? pi0 - im[0][k] : im[0][k] + pi0;
            float sr1 = up ? pr1 - re[1][k] : re[1][k] + pr1;
            float si1 = up ? pi1 - im[1][k] : im[1][k] + pi1;
            re[0][k] = sr0 * wm.x - si0 * wm.y;
            im[0][k] = sr0 * wm.y + si0 * wm.x;
            re[1][k] = sr1 * wm.x - si1 * wm.y;
            im[1][k] = sr1 * wm.y + si1 * wm.x;
        }
    }
}

// 128-pt DIT FFT x2: input slot i holds x[rev7(i)]; natural output. Two lines.
__device__ __forceinline__ void fft128x2_dit(float re[2][4], float im[2][4], int t,
                                             const float2* __restrict__ tw)
{
#pragma unroll
    for (int h = 1; h <= 16; h <<= 1) {
        bool up = (t & h) != 0;
        int idx = (t & (h - 1)) * (64 / h);
        float2 wv = tw[idx];
#pragma unroll
        for (int k = 0; k < 4; k++) {
            float pr0 = __shfl_xor_sync(0xffffffffu, re[0][k], h);
            float pi0 = __shfl_xor_sync(0xffffffffu, im[0][k], h);
            float pr1 = __shfl_xor_sync(0xffffffffu, re[1][k], h);
            float pi1 = __shfl_xor_sync(0xffffffffu, im[1][k], h);
#pragma unroll
            for (int j = 0; j < 2; j++) {
                float pr = j ? pr1 : pr0, pi = j ? pi1 : pi0;
                float mr = up ? re[j][k] : pr;
                float mi = up ? im[j][k] : pi;
                float ur = up ? pr : re[j][k];
                float ui = up ? pi : im[j][k];
                float wr = wv.x * mr - wv.y * mi;
                float wi = wv.x * mi + wv.y * mr;
                re[j][k] = up ? ur - wr : ur + wr;
                im[j][k] = up ? ui - wi : ui + wi;
            }
        }
    }
    {
        float2 wv = tw[2 * t];
#pragma unroll
        for (int j = 0; j < 2; j++) {
            float wr, wi, ur, ui;
            wr = wv.x * re[j][1] - wv.y * im[j][1];
            wi = wv.x * im[j][1] + wv.y * re[j][1];
            ur = re[j][0]; ui = im[j][0];
            re[j][0] = ur + wr; im[j][0] = ui + wi;
            re[j][1] = ur - wr; im[j][1] = ui - wi;
            wr = wv.x * re[j][3] - wv.y * im[j][3];
            wi = wv.x * im[j][3] + wv.y * re[j][3];
            ur = re[j][2]; ui = im[j][2];
            re[j][2] = ur + wr; im[j][2] = ui + wi;
            re[j][3] = ur - wr; im[j][3] = ui - wi;
        }
    }
    {
        float2 w1 = tw[t], w2 = tw[t + 32];
#pragma unroll
        for (int j = 0; j < 2; j++) {
            float wr, wi, ur, ui;
            wr = w1.x * re[j][2] - w1.y * im[j][2];
            wi = w1.x * im[j][2] + w1.y * re[j][2];
            ur = re[j][0]; ui = im[j][0];
            re[j][0] = ur + wr; im[j][0] = ui + wi;
            re[j][2] = ur - wr; im[j][2] = ui - wi;
            wr = w2.x * re[j][3] - w2.y * im[j][3];
            wi = w2.x * im[j][3] + w2.y * re[j][3];
            ur = re[j][1]; ui = im[j][1];
            re[j][1] = ur + wr; im[j][1] = ui + wi;
            re[j][3] = ur - wr; im[j][3] = ui - wi;
        }
    }
}

// Kernel A: per (b,x) plane [y][z]. Z-FFT (DIF x2) -> transpose at column
// rev7(y) -> Y-FFT (DIT x2, natural output) -> straight to global [b][fz][x][fy].
__global__ __launch_bounds__(1024, 1)
void k_fft_zy(const float* __restrict__ ref, const float* __restrict__ pred)
{
    extern __shared__ float2 sV[];          // 128 x S2
    __shared__ float2 tw[64];

    int tid = threadIdx.x, t = tid & 31, w = tid >> 5;
    if (tid < 64) {
        float s, c;
        sincosf(-PIF * (float)tid / 64.f, &s, &c);
        tw[tid] = make_float2(c, s);
    }
    __syncthreads();

    int b = blockIdx.x >> 7, x = blockIdx.x & 127;
    size_t base = ((size_t)(b * 128 + x)) << 14;

    for (int l = 0; l < 4; l += 2) {
        int y0 = w * 4 + l, y1 = y0 + 1;
        float re[2][4], im[2][4];
#pragma unroll
        for (int k = 0; k < 4; k++) {
            int z = t + 32 * k;
            re[0][k] = ref[base + y0 * 128 + z];
            im[0][k] = pred[base + y0 * 128 + z];
            re[1][k] = ref[base + y1 * 128 + z];
            im[1][k] = pred[base + y1 * 128 + z];
        }
        fft128x2(re, im, t, tw);
        int c0 = rev7(y0), c1 = rev7(y1);
#pragma unroll
        for (int k = 0; k < 4; k++) {
            sV[(t + 32 * k) * S2 + c0] = make_float2(re[0][k], im[0][k]);  // CF
            sV[(t + 32 * k) * S2 + c1] = make_float2(re[1][k], im[1][k]);
        }
    }
    __syncthreads();

    for (int l = 0; l < 4; l += 2) {
        int p0 = w * 4 + l, p1 = p0 + 1;
        float re[2][4], im[2][4];
#pragma unroll
        for (int k = 0; k < 4; k++) {
            float2 v0 = sV[p0 * S2 + t + 32 * k];    // CF
            float2 v1 = sV[p1 * S2 + t + 32 * k];
            re[0][k] = v0.x; im[0][k] = v0.y;
            re[1][k] = v1.x; im[1][k] = v1.y;
        }
        fft128x2_dit(re, im, t, tw);
        size_t ob0 = (((size_t)(b * 128 + rev7(p0))) << 14) + ((size_t)x << 7);
        size_t ob1 = (((size_t)(b * 128 + rev7(p1))) << 14) + ((size_t)x << 7);
#pragma unroll
        for (int k = 0; k < 4; k++) {
            g_fft[ob0 + t + 32 * k] = make_float2(re[0][k], im[0][k]);   // coalesced
            g_fft[ob1 + t + 32 * k] = make_float2(re[1][k], im[1][k]);
        }
    }
}

// Accumulate the (cross/2, S, D) decomposition:
// cross = 2*(kx*my + ky*mx); p1 = S + 2D; p2 = S - 2D
// with S = kx^2+ky^2+mx^2+my^2, D = kx*mx - ky*my.
__device__ __forceinline__ void accumSD(float2 gk, float2 gm,
                                        float& cA, float& sA, float& dA)
{
    cA += gk.x * gm.y + gk.y * gm.x;
    sA += gk.x * gk.x + gk.y * gk.y + gm.x * gm.x + gm.y * gm.y;
    dA += gk.x * gm.x - gk.y * gm.y;
}

// Kernel B: fused X-FFT + Hermitian pairing + 4-way mirror fold + reduction.
// Grid: 8 b x 256 r (as round 10). Single-line FFT phase; S/D product;
// warp-shuffle bins flush.
__global__ __launch_bounds__(1024, 2)
void k_fx_reduce(float* __restrict__ out)
{
    extern __shared__ float2 smB2[];
    float2* sP = smB2;                 // 128 x W2
    float2* sQ = smB2 + 128 * W2;
    __shared__ float bins[3 * 65 * 32];
    __shared__ float2 tw[64];
    __shared__ double ssum[512];
    __shared__ bool sLast;
    __shared__ short s_mc[17];    // rep col -> mirror col
    __shared__ int   s_sy2[17];   // rep col -> fy^2

    int tid = threadIdx.x, t = tid & 31, w = tid >> 5;
    if (tid < 64) {
        float s, c;
        sincosf(-PIF * (float)tid / 64.f, &s, &c);
        tw[tid] = make_float2(c, s);
    }
    for (int i = tid; i < 3 * 65 * 32; i += 1024) bins[i] = 0.f;
    if (tid == 0) sLast = false;

    int bi = blockIdx.x;
    int b  = bi >> 8;
    int r  = bi & 255;
    bool special = (r >= 252);
    int g  = special ? (r - 252) : (r & 3);
    int fz = special ? 0 : (1 + (r >> 2));
    int fzQ = special ? 64 : (128 - fz);

    const int rep_lo = (g == 0) ? 0 : 17 + (g - 1) * 16;       // 0,17,33,49
    const int nrep   = (g == 0) ? 17 : 16;
    const int fyA_hi = rep_lo + nrep - 1;                      // 16,32,48,64
    const int fyB_lo = (g == 0) ? 112 : (g == 1) ? 96 : (g == 2) ? 80 : 65;
    const int fyB_hi = (g == 3) ? 79 : fyB_lo + 15;
    const int Kg     = (g == 0) ? 144 : (g == 1) ? 127 : (g == 2) ? 111 : 95;
    float wgt = special ? 1.f : 2.f;

    if (tid < nrep) {
        int c = tid;
        int fy = rep_lo + c;
        s_sy2[c] = fy * fy;
        bool self = (fy == 0 || fy == 64);
        s_mc[c] = (short)(self ? c : (Kg - 128 + fy));
    }
    __syncthreads();

    // float4 segment loads: 17 fy-pairs per x-row (9 covering segA, 8 segB)
    size_t basP = ((size_t)(b * 128 + fz )) << 14;
    size_t basQ = ((size_t)(b * 128 + fzQ)) << 14;
    const int paA = rep_lo >> 1, pbB = fyB_lo >> 1;
    for (int n = tid; n < 128 * 17; n += 1024) {
        int x = n / 17;                      // constant divisor -> mul-hi
        int pi = n - x * 17;
        int fy0 = ((pi < 9) ? (paA + pi) : (pbB + pi - 9)) << 1;
        size_t off = ((size_t)x << 7) + fy0;
        float4 vP = *reinterpret_cast<const float4*>(&g_fft[basP + off]);
        float4 vQ = *reinterpret_cast<const float4*>(&g_fft[basQ + off]);
#pragma unroll
        for (int e = 0; e < 2; e++) {
            int fy = fy0 + e;
            int col = -1;
            if (fy >= rep_lo && fy <= fyA_hi)      col = fy - rep_lo;
            else if (fy >= fyB_lo && fy <= fyB_hi) col = Kg - fy;
            if (col >= 0) {
                sP[x * W2 + col] = e ? make_float2(vP.z, vP.w) : make_float2(vP.x, vP.y);
                sQ[x * W2 + col] = e ? make_float2(vQ.z, vQ.w) : make_float2(vQ.x, vQ.y);
            }
        }
    }
    __syncthreads();

    // X-FFT all P and Q columns (single-line, reg-light)
    const int ncols = (g == 0) ? 33 : (g == 3) ? 31 : 32;
    for (int idx = w; idx < 2 * ncols; idx += 32) {
        bool isQ = (idx >= ncols);
        float2* T = isQ ? sQ : sP;
        int c = isQ ? (idx - ncols) : idx;
        float re[4], im[4];
#pragma unroll
        for (int k = 0; k < 4; k++) {
            float2 v = T[(t + 32 * k) * W2 + c];
            re[k] = v.x; im[k] = v.y;
        }
        fft128(re, im, t, tw);
        __syncwarp();
#pragma unroll
        for (int k = 0; k < 4; k++)
            T[(t + 32 * k) * W2 + c] = make_float2(re[k], im[k]);  // slot p = X[rev7(p)]
    }
    __syncthreads();

    // Product + 4-way mirror fold + shell binning (S/D decomposition)
    int nrepTot = 65 * nrep;
    int total = special ? (nrepTot << 1) : nrepTot;
    for (int n = tid; n < total; n += 1024) {
        int m = n, half = 0;
        if (special && m >= nrepTot) { m -= nrepTot; half = 1; }
        int fx, c;
        if (g == 0) { fx = m / 17; c = m - fx * 17; }   // constant divisor
        else        { fx = m >> 4; c = m & 15; }
        int mc = s_mc[c];
        int xr = (128 - fx) & 127;
        int px  = rev7(fx);
        int pxr = rev7(xr);
        bool fxSelf = (fx == 0 || fx == 64);
        bool cSelf  = (mc == c);

        float2* Tm = half ? sQ : sP;                 // main tile
        float2* Tp = special ? Tm : sQ;              // partner tile
        int szsq = special ? (half ? 4096 : 0) : fz * fz;

        float cA = 0.f, sA = 0.f, dA = 0.f;
        accumSD(Tm[px * W2 + c],  Tp[pxr * W2 + mc], cA, sA, dA);       // ( fx, fy)
        if (!fxSelf)
            accumSD(Tm[pxr * W2 + c],  Tp[px * W2 + mc], cA, sA, dA);   // (-fx, fy)
        if (!cSelf) {
            accumSD(Tm[px * W2 + mc],  Tp[pxr * W2 + c], cA, sA, dA);   // ( fx,-fy)
            if (!fxSelf)
                accumSD(Tm[pxr * W2 + mc], Tp[px * W2 + c], cA, sA, dA); // (-fx,-fy)
        }
        float cr = 2.f * cA;
        float d2v = 2.f * dA;
        float p1 = sA + d2v;
        float p2 = sA - d2v;

        int r2 = fx * fx + s_sy2[c] + szsq;
        int s = min(64, (int)sqrtf((float)r2));
        atomicAdd(&bins[(0 * 65 + s) * 32 + t], cr);
        atomicAdd(&bins[(1 * 65 + s) * 32 + t], p1);
        atomicAdd(&bins[(2 * 65 + s) * 32 + t], p2);
    }
    __syncthreads();

    // Warp-per-row conflict-free flush: lane j reads bins[i*32+j], shfl reduce
    for (int i = w; i < 3 * 65; i += 32) {
        float v = bins[i * 32 + t];
#pragma unroll
        for (int off = 16; off > 0; off >>= 1)
            v += __shfl_down_sync(0xffffffffu, v, off);
        if (t == 0) {
            int comp = i / 65, s = i - comp * 65;
            if (s < 64) atomicAdd(&g_acc[b][s][comp], (double)(v * wgt));
        }
    }

    // ---- last-block fused loss + state reset ----
    __threadfence();
    __syncthreads();
    if (tid == 0) {
        unsigned done = atomicAdd(&g_ctr, 1u);
        sLast = (done == gridDim.x - 1);
    }
    __syncthreads();
    if (!sLast) return;

    if (tid < 512) {
        int bb = tid >> 6, s = tid & 63;
        double num = g_acc[bb][s][0];
        double d1  = g_acc[bb][s][1];
        double d2  = g_acc[bb][s][2];
        double fsc = num / (sqrt(d1 * d2) + 1e-8);
        ssum[tid] = fsc * fsc;
    }
    __syncthreads();
    for (int off = 256; off > 0; off >>= 1) {
        if (tid < off) ssum[tid] += ssum[tid + off];
        __syncthreads();
    }
    if (tid == 0) out[0] = (float)(1.0 - ssum[0] / 512.0);
    __syncthreads();
    double* accf = &g_acc[0][0][0];
    for (int i = tid; i < 8 * 65 * 3; i += 1024) accf[i] = 0.0;
    if (tid == 0) g_ctr = 0;
}

extern "C" void kernel_launch(void* const* d_in, const int* in_sizes, int n_in,
                              void* d_out, int out_size)
{
    const float* ref  = (const float*)d_in[0];
    const float* pred = (const float*)d_in[1];
    float* out = (float*)d_out;

    cudaFuncSetAttribute(k_fft_zy,    cudaFuncAttributeMaxDynamicSharedMemorySize, SMEM_A);
    cudaFuncSetAttribute(k_fx_reduce, cudaFuncAttributeMaxDynamicSharedMemorySize, SMEM_B);

    k_fft_zy<<<1024, 1024, SMEM_A>>>(ref, pred);
    k_fx_reduce<<<2048, 1024, SMEM_B>>>(out);
}

// round 17
// speedup vs baseline: 1.0617x; 1.0617x over previous
#include <cuda_runtime.h>
#include <cuda_fp16.h>
#include <math.h>

// ---------------------------------------------------------------------------
// FSC loss, round 15: identical structure to round 13 (best, 213.5us), with
// the inter-kernel scratch stored as __half2 (67 MB -> L2-resident) instead
// of float2 (134 MB, spills L2). A: DIF x2 -> rev7-transpose -> DIT x2 ->
// half2 stores. B: half2 loads -> fp32 smem tiles -> fused X-FFT + Hermitian
// pairing + 4-way mirror fold + shell reduction + loss.
// ---------------------------------------------------------------------------

#define S2   129      // kernel A transpose row stride (float2)
#define W2   33       // kernel B tile row stride (float2)
#define SMEM_A (128 * S2 * 8)                 // 132096 B
#define SMEM_B (2 * 128 * W2 * 8)             // 67584 B
#define PIF 3.14159265358979323846f

static __device__ __half2 g_fft[8u * 128u * 128u * 128u];  // 67 MB scratch
static __device__ double g_acc[8][65][3];                  // num, d1, d2
static __device__ unsigned int g_ctr = 0;

__device__ __forceinline__ int rev7(int i) { return (int)(__brev((unsigned)i) >> 25); }

__device__ __forceinline__ float2 h2f(unsigned int u) {
    __half2 h = *reinterpret_cast<__half2*>(&u);
    return __half22float2(h);
}

// 128-pt DIF FFT (single): natural input; output slot i holds X[rev7(i)].
__device__ __forceinline__ void fft128(float re[4], float im[4], int t,
                                       const float2* __restrict__ tw)
{
    {
        float2 w1 = tw[t], w2 = tw[t + 32];
        float ar, ai;
        ar = re[0] - re[2]; ai = im[0] - im[2];
        re[0] += re[2];     im[0] += im[2];
        re[2] = ar * w1.x - ai * w1.y; im[2] = ar * w1.y + ai * w1.x;
        ar = re[1] - re[3]; ai = im[1] - im[3];
        re[1] += re[3];     im[1] += im[3];
        re[3] = ar * w2.x - ai * w2.y; im[3] = ar * w2.y + ai * w2.x;
    }
    {
        float2 w3 = tw[2 * t];
        float ar, ai;
        ar = re[0] - re[1]; ai = im[0] - im[1];
        re[0] += re[1];     im[0] += im[1];
        re[1] = ar * w3.x - ai * w3.y; im[1] = ar * w3.y + ai * w3.x;
        ar = re[2] - re[3]; ai = im[2] - im[3];
        re[2] += re[3];     im[2] += im[3];
        re[3] = ar * w3.x - ai * w3.y; im[3] = ar * w3.y + ai * w3.x;
    }
#pragma unroll
    for (int m = 16; m >= 1; m >>= 1) {
        bool up = (t & m) != 0;
        int idx = up ? (64 / m) * (t & (m - 1)) : 0;
        float2 wm = tw[idx];
#pragma unroll
        for (int k = 0; k < 4; k++) {
            float pr = __shfl_xor_sync(0xffffffffu, re[k], m);
            float pi = __shfl_xor_sync(0xffffffffu, im[k], m);
            float sr = up ? pr - re[k] : re[k] + pr;
            float si = up ? pi - im[k] : im[k] + pi;
            re[k] = sr * wm.x - si * wm.y;
            im[k] = sr * wm.y + si * wm.x;
        }
    }
}

// 128-pt DIF FFT x2: two independent lines interleaved (ILP pairing).
__device__ __forceinline__ void fft128x2(float re[2][4], float im[2][4], int t,
                                         const float2* __restrict__ tw)
{
    {
        float2 w1 = tw[t], w2 = tw[t + 32];
#pragma unroll
        for (int j = 0; j < 2; j++) {
            float ar, ai;
            ar = re[j][0] - re[j][2]; ai = im[j][0] - im[j][2];
            re[j][0] += re[j][2];     im[j][0] += im[j][2];
            re[j][2] = ar * w1.x - ai * w1.y; im[j][2] = ar * w1.y + ai * w1.x;
            ar = re[j][1] - re[j][3]; ai = im[j][1] - im[j][3];
            re[j][1] += re[j][3];     im[j][1] += im[j][3];
            re[j][3] = ar * w2.x - ai * w2.y; im[j][3] = ar * w2.y + ai * w2.x;
        }
    }
    {
        float2 w3 = tw[2 * t];
#pragma unroll
        for (int j = 0; j < 2; j++) {
            float ar, ai;
            ar = re[j][0] - re[j][1]; ai = im[j][0] - im[j][1];
            re[j][0] += re[j][1];     im[j][0] += im[j][1];
            re[j][1] = ar * w3.x - ai * w3.y; im[j][1] = ar * w3.y + ai * w3.x;
            ar = re[j][2] - re[j][3]; ai = im[j][2] - im[j][3];
            re[j][2] += re[j][3];     im[j][2] += im[j][3];
            re[j][3] = ar * w3.x - ai * w3.y; im[j][3] = ar * w3.y + ai * w3.x;
        }
    }
#pragma unroll
    for (int m = 16; m >= 1; m >>= 1) {
        bool up = (t & m) != 0;
        int idx = up ? (64 / m) * (t & (m - 1)) : 0;
        float2 wm = tw[idx];
#pragma unroll
        for (int k = 0; k < 4; k++) {
            float pr0 = __shfl_xor_sync(0xffffffffu, re[0][k], m);
            float pi0 = __shfl_xor_sync(0xffffffffu, im[0][k], m);
            float pr1 = __shfl_xor_sync(0xffffffffu, re[1][k], m);
            float pi1 = __shfl_xor_sync(0xffffffffu, im[1][k], m);
            float sr0 = up ? pr0 - re[0][k] : re[0][k] + pr0;
            float si0 = up ? pi0 - im[0][k] : im[0][k] + pi0;
            float sr1 = up ? pr1 - re[1][k] : re[1][k] + pr1;
            float si1 = up ? pi1 - im[1][k] : im[1][k] + pi1;
            re[0][k] = sr0 * wm.x - si0 * wm.y;
            im[0][k] = sr0 * wm.y + si0 * wm.x;
            re[1][k] = sr1 * wm.x - si1 * wm.y;
            im[1][k] = sr1 * wm.y + si1 * wm.x;
        }
    }
}

// 128-pt DIT FFT x2: input slot i holds x[rev7(i)]; natural output. Two lines.
__device__ __forceinline__ void fft128x2_dit(float re[2][4], float im[2][4], int t,
                                             const float2* __restrict__ tw)
{
#pragma unroll
    for (int h = 1; h <= 16; h <<= 1) {
        bool up = (t & h) != 0;
        int idx = (t & (h - 1)) * (64 / h);
        float2 wv = tw[idx];
#pragma unroll
        for (int k = 0; k < 4; k++) {
            float pr0 = __shfl_xor_sync(0xffffffffu, re[0][k], h);
            float pi0 = __shfl_xor_sync(0xffffffffu, im[0][k], h);
            float pr1 = __shfl_xor_sync(0xffffffffu, re[1][k], h);
            float pi1 = __shfl_xor_sync(0xffffffffu, im[1][k], h);
#pragma unroll
            for (int j = 0; j < 2; j++) {
                float pr = j ? pr1 : pr0, pi = j ? pi1 : pi0;
                float mr = up ? re[j][k] : pr;
                float mi = up ? im[j][k] : pi;
                float ur = up ? pr : re[j][k];
                float ui = up ? pi : im[j][k];
                float wr = wv.x * mr - wv.y * mi;
                float wi = wv.x * mi + wv.y * mr;
                re[j][k] = up ? ur - wr : ur + wr;
                im[j][k] = up ? ui - wi : ui + wi;
            }
        }
    }
    {
        float2 wv = tw[2 * t];
#pragma unroll
        for (int j = 0; j < 2; j++) {
            float wr, wi, ur, ui;
            wr = wv.x * re[j][1] - wv.y * im[j][1];
            wi = wv.x * im[j][1] + wv.y * re[j][1];
            ur = re[j][0]; ui = im[j][0];
            re[j][0] = ur + wr; im[j][0] = ui + wi;
            re[j][1] = ur - wr; im[j][1] = ui - wi;
            wr = wv.x * re[j][3] - wv.y * im[j][3];
            wi = wv.x * im[j][3] + wv.y * re[j][3];
            ur = re[j][2]; ui = im[j][2];
            re[j][2] = ur + wr; im[j][2] = ui + wi;
            re[j][3] = ur - wr; im[j][3] = ui - wi;
        }
    }
    {
        float2 w1 = tw[t], w2 = tw[t + 32];
#pragma unroll
        for (int j = 0; j < 2; j++) {
            float wr, wi, ur, ui;
            wr = w1.x * re[j][2] - w1.y * im[j][2];
            wi = w1.x * im[j][2] + w1.y * re[j][2];
            ur = re[j][0]; ui = im[j][0];
            re[j][0] = ur + wr; im[j][0] = ui + wi;
            re[j][2] = ur - wr; im[j][2] = ui - wi;
            wr = w2.x * re[j][3] - w2.y * im[j][3];
            wi = w2.x * im[j][3] + w2.y * re[j][3];
            ur = re[j][1]; ui = im[j][1];
            re[j][1] = ur + wr; im[j][1] = ui + wi;
            re[j][3] = ur - wr; im[j][3] = ui - wi;
        }
    }
}

// Kernel A: per (b,x) plane [y][z]. Z-FFT (DIF x2) -> transpose at column
// rev7(y) -> Y-FFT (DIT x2, natural output) -> half2 stores to global
// [b][fz][x][fy].
__global__ __launch_bounds__(1024, 1)
void k_fft_zy(const float* __restrict__ ref, const float* __restrict__ pred)
{
    extern __shared__ float2 sV[];          // 128 x S2
    __shared__ float2 tw[64];

    int tid = threadIdx.x, t = tid & 31, w = tid >> 5;
    if (tid < 64) {
        float s, c;
        sincosf(-PIF * (float)tid / 64.f, &s, &c);
        tw[tid] = make_float2(c, s);
    }
    __syncthreads();

    int b = blockIdx.x >> 7, x = blockIdx.x & 127;
    size_t base = ((size_t)(b * 128 + x)) << 14;

    for (int l = 0; l < 4; l += 2) {
        int y0 = w * 4 + l, y1 = y0 + 1;
        float re[2][4], im[2][4];
#pragma unroll
        for (int k = 0; k < 4; k++) {
            int z = t + 32 * k;
            re[0][k] = ref[base + y0 * 128 + z];
            im[0][k] = pred[base + y0 * 128 + z];
            re[1][k] = ref[base + y1 * 128 + z];
            im[1][k] = pred[base + y1 * 128 + z];
        }
        fft128x2(re, im, t, tw);
        int c0 = rev7(y0), c1 = rev7(y1);
#pragma unroll
        for (int k = 0; k < 4; k++) {
            sV[(t + 32 * k) * S2 + c0] = make_float2(re[0][k], im[0][k]);  // CF
            sV[(t + 32 * k) * S2 + c1] = make_float2(re[1][k], im[1][k]);
        }
    }
    __syncthreads();

    for (int l = 0; l < 4; l += 2) {
        int p0 = w * 4 + l, p1 = p0 + 1;
        float re[2][4], im[2][4];
#pragma unroll
        for (int k = 0; k < 4; k++) {
            float2 v0 = sV[p0 * S2 + t + 32 * k];    // CF
            float2 v1 = sV[p1 * S2 + t + 32 * k];
            re[0][k] = v0.x; im[0][k] = v0.y;
            re[1][k] = v1.x; im[1][k] = v1.y;
        }
        fft128x2_dit(re, im, t, tw);
        size_t ob0 = (((size_t)(b * 128 + rev7(p0))) << 14) + ((size_t)x << 7);
        size_t ob1 = (((size_t)(b * 128 + rev7(p1))) << 14) + ((size_t)x << 7);
#pragma unroll
        for (int k = 0; k < 4; k++) {
            g_fft[ob0 + t + 32 * k] = __floats2half2_rn(re[0][k], im[0][k]);  // coalesced
            g_fft[ob1 + t + 32 * k] = __floats2half2_rn(re[1][k], im[1][k]);
        }
    }
}

__device__ __forceinline__ void accum3(float2 gk, float2 gm,
                                       float& cr, float& p1, float& p2)
{
    float ar = gk.x + gm.x, ai = gk.y - gm.y;
    float br = gk.x - gm.x, bi = gk.y + gm.y;
    cr += ar * bi - ai * br;
    p1 += ar * ar + ai * ai;
    p2 += br * br + bi * bi;
}

// Kernel B: fused X-FFT + Hermitian pairing + 4-way mirror fold + reduction.
// Grid: 8 b x 256 r. r < 252: fz = 1 + r/4 (1..63), g = r&3, weight 2.
// r >= 252: special block g = r-252, P = plane 0, Q = plane 64, each
// self-paired, weight 1. Half2 scratch loads -> fp32 smem tiles.
__global__ __launch_bounds__(1024, 2)
void k_fx_reduce(float* __restrict__ out)
{
    extern __shared__ float2 smB2[];
    float2* sP = smB2;                 // 128 x W2
    float2* sQ = smB2 + 128 * W2;
    __shared__ float bins[3 * 65 * 32];
    __shared__ float2 tw[64];
    __shared__ double ssum[512];
    __shared__ bool sLast;
    __shared__ short s_mc[17];    // rep col -> mirror col
    __shared__ int   s_sy2[17];   // rep col -> fy^2

    int tid = threadIdx.x, t = tid & 31, w = tid >> 5;
    if (tid < 64) {
        float s, c;
        sincosf(-PIF * (float)tid / 64.f, &s, &c);
        tw[tid] = make_float2(c, s);
    }
    for (int i = tid; i < 3 * 65 * 32; i += 1024) bins[i] = 0.f;
    if (tid == 0) sLast = false;

    int bi = blockIdx.x;
    int b  = bi >> 8;
    int r  = bi & 255;
    bool special = (r >= 252);
    int g  = special ? (r - 252) : (r & 3);
    int fz = special ? 0 : (1 + (r >> 2));
    int fzQ = special ? 64 : (128 - fz);

    const int rep_lo = (g == 0) ? 0 : 17 + (g - 1) * 16;       // 0,17,33,49
    const int nrep   = (g == 0) ? 17 : 16;
    const int fyA_hi = rep_lo + nrep - 1;                      // 16,32,48,64
    const int fyB_lo = (g == 0) ? 112 : (g == 1) ? 96 : (g == 2) ? 80 : 65;
    const int fyB_hi = (g == 3) ? 79 : fyB_lo + 15;
    const int Kg     = (g == 0) ? 144 : (g == 1) ? 127 : (g == 2) ? 111 : 95;
    float wgt = special ? 1.f : 2.f;

    if (tid < nrep) {
        int c = tid;
        int fy = rep_lo + c;
        s_sy2[c] = fy * fy;
        bool self = (fy == 0 || fy == 64);
        s_mc[c] = (short)(self ? c : (Kg - 128 + fy));
    }
    __syncthreads();

    // uint2 segment loads (2 half2 elements): 17 fy-pairs per x-row
    size_t basP = ((size_t)(b * 128 + fz )) << 14;
    size_t basQ = ((size_t)(b * 128 + fzQ)) << 14;
    const int paA = rep_lo >> 1, pbB = fyB_lo >> 1;
    for (int n = tid; n < 128 * 17; n += 1024) {
        int x = n / 17;                      // constant divisor -> mul-hi
        int pi = n - x * 17;
        int fy0 = ((pi < 9) ? (paA + pi) : (pbB + pi - 9)) << 1;
        size_t off = ((size_t)x << 7) + fy0;
        uint2 vP = *reinterpret_cast<const uint2*>(&g_fft[basP + off]);
        uint2 vQ = *reinterpret_cast<const uint2*>(&g_fft[basQ + off]);
#pragma unroll
        for (int e = 0; e < 2; e++) {
            int fy = fy0 + e;
            int col = -1;
            if (fy >= rep_lo && fy <= fyA_hi)      col = fy - rep_lo;
            else if (fy >= fyB_lo && fy <= fyB_hi) col = Kg - fy;
            if (col >= 0) {
                sP[x * W2 + col] = h2f(e ? vP.y : vP.x);
                sQ[x * W2 + col] = h2f(e ? vQ.y : vQ.x);
            }
        }
    }
    __syncthreads();

    // X-FFT all P and Q columns; pairs (w, w+32) interleaved for ILP
    const int ncols = (g == 0) ? 33 : (g == 3) ? 31 : 32;
    const int ntot = 2 * ncols;
    {
        int idx0 = w, idx1 = w + 32;
        bool isQ0 = (idx0 >= ncols);
        float2* T0 = isQ0 ? sQ : sP;
        int c0 = isQ0 ? (idx0 - ncols) : idx0;
        if (idx1 < ntot) {
            bool isQ1 = (idx1 >= ncols);
            float2* T1 = isQ1 ? sQ : sP;
            int c1 = isQ1 ? (idx1 - ncols) : idx1;
            float re[2][4], im[2][4];
#pragma unroll
            for (int k = 0; k < 4; k++) {
                float2 v0 = T0[(t + 32 * k) * W2 + c0];
                float2 v1 = T1[(t + 32 * k) * W2 + c1];
                re[0][k] = v0.x; im[0][k] = v0.y;
                re[1][k] = v1.x; im[1][k] = v1.y;
            }
            fft128x2(re, im, t, tw);
            __syncwarp();
#pragma unroll
            for (int k = 0; k < 4; k++) {
                T0[(t + 32 * k) * W2 + c0] = make_float2(re[0][k], im[0][k]);
                T1[(t + 32 * k) * W2 + c1] = make_float2(re[1][k], im[1][k]);
            }
        } else {
            float re[4], im[4];
#pragma unroll
            for (int k = 0; k < 4; k++) {
                float2 v = T0[(t + 32 * k) * W2 + c0];
                re[k] = v.x; im[k] = v.y;
            }
            fft128(re, im, t, tw);
            __syncwarp();
#pragma unroll
            for (int k = 0; k < 4; k++)
                T0[(t + 32 * k) * W2 + c0] = make_float2(re[k], im[k]);
        }
        int idx2 = w + 64;
        if (idx2 < ntot) {                    // g==0 leftovers (warps 0,1)
            bool isQ2 = (idx2 >= ncols);
            float2* T2 = isQ2 ? sQ : sP;
            int c2 = isQ2 ? (idx2 - ncols) : idx2;
            float re[4], im[4];
#pragma unroll
            for (int k = 0; k < 4; k++) {
                float2 v = T2[(t + 32 * k) * W2 + c2];
                re[k] = v.x; im[k] = v.y;
            }
            fft128(re, im, t, tw);
            __syncwarp();
#pragma unroll
            for (int k = 0; k < 4; k++)
                T2[(t + 32 * k) * W2 + c2] = make_float2(re[k], im[k]);
        }
    }
    __syncthreads();

    // Product + 4-way mirror fold + shell binning
    int nrepTot = 65 * nrep;
    int total = special ? (nrepTot << 1) : nrepTot;
    for (int n = tid; n < total; n += 1024) {
        int m = n, half = 0;
        if (special && m >= nrepTot) { m -= nrepTot; half = 1; }
        int fx, c;
        if (g == 0) { fx = m / 17; c = m - fx * 17; }   // constant divisor
        else        { fx = m >> 4; c = m & 15; }
        int mc = s_mc[c];
        int xr = (128 - fx) & 127;
        int px  = rev7(fx);
        int pxr = rev7(xr);
        bool fxSelf = (fx == 0 || fx == 64);
        bool cSelf  = (mc == c);

        float2* Tm = half ? sQ : sP;                 // main tile
        float2* Tp = special ? Tm : sQ;              // partner tile
        int szsq = special ? (half ? 4096 : 0) : fz * fz;

        float cr = 0.f, p1 = 0.f, p2 = 0.f;
        accum3(Tm[px * W2 + c],  Tp[pxr * W2 + mc], cr, p1, p2);       // ( fx, fy)
        if (!fxSelf)
            accum3(Tm[pxr * W2 + c],  Tp[px * W2 + mc], cr, p1, p2);   // (-fx, fy)
        if (!cSelf) {
            accum3(Tm[px * W2 + mc],  Tp[pxr * W2 + c], cr, p1, p2);   // ( fx,-fy)
            if (!fxSelf)
                accum3(Tm[pxr * W2 + mc], Tp[px * W2 + c], cr, p1, p2); // (-fx,-fy)
        }

        int r2 = fx * fx + s_sy2[c] + szsq;
        int s = min(64, (int)sqrtf((float)r2));
        atomicAdd(&bins[(0 * 65 + s) * 32 + t], cr);
        atomicAdd(&bins[(1 * 65 + s) * 32 + t], p1);
        atomicAdd(&bins[(2 * 65 + s) * 32 + t], p2);
    }
    __syncthreads();

    for (int i = tid; i < 3 * 65; i += 1024) {
        float acc = 0.f;
#pragma unroll
        for (int j = 0; j < 32; j++) acc += bins[i * 32 + j];
        int comp = i / 65, s = i - comp * 65;
        if (s < 64) atomicAdd(&g_acc[b][s][comp], (double)(acc * wgt));
    }

    // ---- last-block fused loss + state reset ----
    __threadfence();
    __syncthreads();
    if (tid == 0) {
        unsigned done = atomicAdd(&g_ctr, 1u);
        sLast = (done == gridDim.x - 1);
    }
    __syncthreads();
    if (!sLast) return;

    if (tid < 512) {
        int bb = tid >> 6, s = tid & 63;
        double num = g_acc[bb][s][0];
        double d1  = g_acc[bb][s][1];
        double d2  = g_acc[bb][s][2];
        double fsc = num / (sqrt(d1 * d2) + 1e-8);
        ssum[tid] = fsc * fsc;
    }
    __syncthreads();
    for (int off = 256; off > 0; off >>= 1) {
        if (tid < off) ssum[tid] += ssum[tid + off];
        __syncthreads();
    }
    if (tid == 0) out[0] = (float)(1.0 - ssum[0] / 512.0);
    __syncthreads();
    double* accf = &g_acc[0][0][0];
    for (int i = tid; i < 8 * 65 * 3; i += 1024) accf[i] = 0.0;
    if (tid == 0) g_ctr = 0;
}

extern "C" void kernel_launch(void* const* d_in, const int* in_sizes, int n_in,
                              void* d_out, int out_size)
{
    const float* ref  = (const float*)d_in[0];
    const float* pred = (const float*)d_in[1];
    float* out = (float*)d_out;

    cudaFuncSetAttribute(k_fft_zy,    cudaFuncAttributeMaxDynamicSharedMemorySize, SMEM_A);
    cudaFuncSetAttribute(k_fx_reduce, cudaFuncAttributeMaxDynamicSharedMemorySize, SMEM_B);

    k_fft_zy<<<1024, 1024, SMEM_A>>>(ref, pred);
    k_fx_reduce<<<2048, 1024, SMEM_B>>>(out);
}